// round 6
// baseline (speedup 1.0000x reference)
#include <cuda_runtime.h>
#include <cuda_fp16.h>
#include <cstdint>

// ---------------- problem constants (fixed by the reference) ----------------
#define EMBD   256
#define HIDDEN 256
#define HNUM   8
#define CHD    32
#define BATCH  8
#define NQ     1024
#define ITOT   21760           // 128^2 + 64^2 + 32^2 + 16^2
#define QPW    384             // H*L*P*3
#define GK     256             // K for every GEMM
#define BNH    (BATCH * NQ * HNUM)   // 65536

// ---------------- scratch (no allocations allowed) ----------------
__device__ __half  g_img_p[BATCH * ITOT * HIDDEN];   // projected pyramid, fp16 (~89 MB)
__device__ __half  g_Wt1[HIDDEN * GK];               // W_img^T [N,K] fp16
__device__ __half  g_Wt2[QPW * GK];                  // W_q^T   [N,K] fp16
__device__ __half  g_Wt3[EMBD * GK];                 // W_out^T [N,K] fp16
__device__ float   g_qp[BATCH * NQ * QPW];           // query projection
__device__ float4  g_sw[BNH * 16];                   // 4 corner weights (x attn)
__device__ int4    g_si[BNH * 16];                   // 4 corner indices (x HIDDEN)
__device__ float   g_hidden[BATCH * NQ * HIDDEN];    // sampled context

__constant__ int c_sh[4]    = {128, 64, 32, 16};
__constant__ int c_start[4] = {0, 16384, 20480, 21504};

// ---------------- helpers ----------------
__device__ __forceinline__ void cp16(uint32_t dst, const void* src) {
    asm volatile("cp.async.cg.shared.global [%0], [%1], 16;" :: "r"(dst), "l"(src));
}
__device__ __forceinline__ uint32_t smem_u32(const void* p) {
    uint32_t a;
    asm("{ .reg .u64 t; cvta.to.shared.u64 t, %1; cvt.u32.u64 %0, t; }" : "=r"(a) : "l"(p));
    return a;
}
__device__ __forceinline__ uint32_t pack_h2(float lo, float hi) {
    uint32_t r;
    asm("cvt.rn.f16x2.f32 %0, %1, %2;" : "=r"(r) : "f"(hi), "f"(lo));
    return r;
}

// ============ GEMM1: C_fp16[M,256] = A_fp32[M,256] @ Wt_fp16[256,256]^T + bias ============
// CTA 128x128, 8 warps 2(M)x4(N), warp tile 64x32.  fp16 A+B in smem (pitch 24 halves
// = 48B: LDSM/LDS conflict-free).  A: LDG fp32 -> cvt -> STS fp16 (2-iter reg pipeline);
// B: cp.async.  A fragments via ldmatrix.x4.  3-stage smem.

#define APITCH  24                 // halves per A/B row (16 used + 8 pad)
#define STG_H   (128 * APITCH)     // halves per stage per tile
#define NST     3
#define NKT16   (GK / 16)          // 16

__global__ __launch_bounds__(256) void hgemm16(
    const float* __restrict__ A, const __half* __restrict__ Wt,
    const float* __restrict__ bias, __half* __restrict__ C)
{
    __shared__ __half sA[NST][STG_H];   // 3 * 6 KB
    __shared__ __half sB[NST][STG_H];   // 3 * 6 KB

    const int tid = threadIdx.x;
    const int wid = tid >> 5;
    const int lane = tid & 31;
    const int g = lane >> 2;             // 0..7
    const int tig = lane & 3;            // 0..3
    const int m0 = blockIdx.y * 128;
    const int n0 = blockIdx.x * 128;
    const int wm = (wid & 1) * 64;       // warp M offset
    const int wn = (wid >> 1) * 32;      // warp N offset

    // per-lane ldmatrix offset (halves): row = wm + (lane&15), kcol = (lane>>4)*8
    const uint32_t lds_a_off = (uint32_t)((wm + (lane & 15)) * APITCH + (lane >> 4) * 8) * 2;

    uint32_t sbA[NST], sbB[NST];
    #pragma unroll
    for (int s = 0; s < NST; s++) { sbA[s] = smem_u32(&sA[s][0]); sbB[s] = smem_u32(&sB[s][0]); }

    const int arow = tid >> 1, aseg = tid & 1;          // A/B stage-fill mapping
    const float* Ab = A + (size_t)(m0 + arow) * GK + aseg * 8;
    const __half* Bb = Wt + (size_t)(n0 + arow) * GK + aseg * 8;
    const uint32_t st_off = (uint32_t)(arow * APITCH + aseg * 8) * 2;

    float4 rA[2][2];
    auto ldgA = [&](int kt, int slot) {
        const float* p = Ab + kt * 16;
        rA[slot][0] = *(const float4*)p;
        rA[slot][1] = *(const float4*)(p + 4);
    };
    auto stsA = [&](int buf, int slot) {
        uint4 v;
        v.x = pack_h2(rA[slot][0].x, rA[slot][0].y);
        v.y = pack_h2(rA[slot][0].z, rA[slot][0].w);
        v.z = pack_h2(rA[slot][1].x, rA[slot][1].y);
        v.w = pack_h2(rA[slot][1].z, rA[slot][1].w);
        *(uint4*)((char*)&sA[buf][0] + st_off) = v;
    };
    auto cpB = [&](int buf, int kt) {
        cp16(sbB[buf] + st_off, Bb + kt * 16);
    };

    float acc[4][4][4];
    #pragma unroll
    for (int i = 0; i < 4; i++)
        #pragma unroll
        for (int j = 0; j < 4; j++)
            #pragma unroll
            for (int r = 0; r < 4; r++) acc[i][j][r] = 0.f;

    // prologue
    ldgA(0, 0); ldgA(1, 1);
    cpB(0, 0);  asm volatile("cp.async.commit_group;" ::: "memory");
    cpB(1, 1);  asm volatile("cp.async.commit_group;" ::: "memory");
    stsA(0, 0); ldgA(2, 0);

    int buf = 0;
    #pragma unroll 1
    for (int kt = 0; kt < NKT16; kt++) {
        if (kt < NKT16 - 1) {
            asm volatile("cp.async.wait_group 1;" ::: "memory");
        } else {
            asm volatile("cp.async.wait_group 0;" ::: "memory");
        }
        __syncthreads();

        if (kt + 2 < NKT16) {
            int nb = buf + 2; if (nb >= NST) nb -= NST;
            cpB(nb, kt + 2);
            asm volatile("cp.async.commit_group;" ::: "memory");
        }

        // ---- fragments ----
        uint32_t a[4][4], b[4][2];
        #pragma unroll
        for (int mf = 0; mf < 4; mf++) {
            uint32_t addr = sbA[buf] + lds_a_off + (uint32_t)(mf * 16 * APITCH) * 2;
            asm volatile(
                "ldmatrix.sync.aligned.m8n8.x4.shared.b16 {%0,%1,%2,%3}, [%4];"
                : "=r"(a[mf][0]), "=r"(a[mf][1]), "=r"(a[mf][2]), "=r"(a[mf][3])
                : "r"(addr));
        }
        const __half* Bs = sB[buf];
        #pragma unroll
        for (int nf = 0; nf < 4; nf++) {
            int rb = wn + nf * 8 + g;
            b[nf][0] = *(const uint32_t*)&Bs[rb * APITCH + tig * 2];
            b[nf][1] = *(const uint32_t*)&Bs[rb * APITCH + tig * 2 + 8];
        }
        #pragma unroll
        for (int mf = 0; mf < 4; mf++)
            #pragma unroll
            for (int nf = 0; nf < 4; nf++) {
                asm volatile(
                    "mma.sync.aligned.m16n8k16.row.col.f32.f16.f16.f32 "
                    "{%0,%1,%2,%3}, {%4,%5,%6,%7}, {%8,%9}, {%0,%1,%2,%3};"
                    : "+f"(acc[mf][nf][0]), "+f"(acc[mf][nf][1]),
                      "+f"(acc[mf][nf][2]), "+f"(acc[mf][nf][3])
                    : "r"(a[mf][0]), "r"(a[mf][1]), "r"(a[mf][2]), "r"(a[mf][3]),
                      "r"(b[nf][0]), "r"(b[nf][1]));
            }

        // ---- producers for future stages ----
        if (kt + 1 < NKT16) {
            int nb = buf + 1; if (nb >= NST) nb -= NST;
            stsA(nb, (kt + 1) & 1);
        }
        if (kt + 3 < NKT16) ldgA(kt + 3, (kt + 3) & 1);

        if (++buf == NST) buf = 0;
    }

    // epilogue: bias + fp16 store
    #pragma unroll
    for (int nf = 0; nf < 4; nf++) {
        const int col = n0 + wn + nf * 8 + tig * 2;
        const float2 bb = *(const float2*)(bias + col);
        #pragma unroll
        for (int mf = 0; mf < 4; mf++) {
            const int row = m0 + wm + mf * 16 + g;
            uint32_t h0 = pack_h2(acc[mf][nf][0] + bb.x, acc[mf][nf][1] + bb.y);
            uint32_t h1 = pack_h2(acc[mf][nf][2] + bb.x, acc[mf][nf][3] + bb.y);
            *(uint32_t*)(C + (size_t)row * HIDDEN + col) = h0;
            *(uint32_t*)(C + (size_t)(row + 8) * HIDDEN + col) = h1;
        }
    }
}

// =============== fp16 mma GEMM (R5 kernel, kept for GEMM2/3) ===============
#define ROWPAD  20
#define BPITCH  24
#define A_STG   (128 * ROWPAD)
#define B_STG   (64 * BPITCH)
#define NSTAGE  3
#define NKT     (GK / 16)

__global__ __launch_bounds__(256) void hgemm(
    const float* __restrict__ A, const __half* __restrict__ Wt,
    const float* __restrict__ bias, float* __restrict__ C,
    int M, int N)
{
    __shared__ float  sA[NSTAGE][A_STG];
    __shared__ __half sB[NSTAGE][B_STG];

    const int tid = threadIdx.x;
    const int wid = tid >> 5;
    const int lane = tid & 31;
    const int g = lane >> 2;
    const int tig = lane & 3;
    const int m0 = blockIdx.y * 128;
    const int n0 = blockIdx.x * 64;
    const int wm = (wid & 3) * 32;
    const int wn = (wid >> 2) * 32;

    float acc[2][4][4];
    #pragma unroll
    for (int i = 0; i < 2; i++)
        #pragma unroll
        for (int j = 0; j < 4; j++)
            #pragma unroll
            for (int r = 0; r < 4; r++) acc[i][j][r] = 0.f;

    uint32_t sbA[NSTAGE], sbB[NSTAGE];
    #pragma unroll
    for (int s = 0; s < NSTAGE; s++) {
        sbA[s] = smem_u32(&sA[s][0]);
        sbB[s] = smem_u32(&sB[s][0]);
    }

    auto load_stage = [&](int s, int kt) {
        #pragma unroll
        for (int i = 0; i < 2; i++) {
            int id = tid + i * 256;
            int row = id >> 2, c = id & 3;
            cp16(sbA[s] + (uint32_t)(row * ROWPAD + c * 4) * 4,
                 A + (size_t)(m0 + row) * GK + kt * 16 + c * 4);
        }
        if (tid < 128) {
            int row = tid >> 1, c = tid & 1;
            cp16(sbB[s] + (uint32_t)(row * BPITCH + c * 8) * 2,
                 Wt + (size_t)(n0 + row) * GK + kt * 16 + c * 8);
        }
    };

    load_stage(0, 0);
    asm volatile("cp.async.commit_group;" ::: "memory");
    load_stage(1, 1);
    asm volatile("cp.async.commit_group;" ::: "memory");

    #pragma unroll 1
    for (int kt = 0; kt < NKT; kt++) {
        if (kt < NKT - 1) {
            asm volatile("cp.async.wait_group 1;" ::: "memory");
        } else {
            asm volatile("cp.async.wait_group 0;" ::: "memory");
        }
        __syncthreads();

        if (kt + 2 < NKT) {
            load_stage((kt + 2) % NSTAGE, kt + 2);
            asm volatile("cp.async.commit_group;" ::: "memory");
        }

        const float*  As = sA[kt % NSTAGE];
        const __half* Bs = sB[kt % NSTAGE];

        uint32_t a[2][4], b[4][2];
        #pragma unroll
        for (int mf = 0; mf < 2; mf++) {
            int r = wm + mf * 16 + g;
            a[mf][0] = pack_h2(As[r * ROWPAD + tig * 2], As[r * ROWPAD + tig * 2 + 1]);
            a[mf][1] = pack_h2(As[(r + 8) * ROWPAD + tig * 2], As[(r + 8) * ROWPAD + tig * 2 + 1]);
            a[mf][2] = pack_h2(As[r * ROWPAD + tig * 2 + 8], As[r * ROWPAD + tig * 2 + 9]);
            a[mf][3] = pack_h2(As[(r + 8) * ROWPAD + tig * 2 + 8], As[(r + 8) * ROWPAD + tig * 2 + 9]);
        }
        #pragma unroll
        for (int nf = 0; nf < 4; nf++) {
            int rb = wn + nf * 8 + g;
            b[nf][0] = *(const uint32_t*)&Bs[rb * BPITCH + tig * 2];
            b[nf][1] = *(const uint32_t*)&Bs[rb * BPITCH + tig * 2 + 8];
        }
        #pragma unroll
        for (int mf = 0; mf < 2; mf++)
            #pragma unroll
            for (int nf = 0; nf < 4; nf++) {
                asm volatile(
                    "mma.sync.aligned.m16n8k16.row.col.f32.f16.f16.f32 "
                    "{%0,%1,%2,%3}, {%4,%5,%6,%7}, {%8,%9}, {%0,%1,%2,%3};"
                    : "+f"(acc[mf][nf][0]), "+f"(acc[mf][nf][1]),
                      "+f"(acc[mf][nf][2]), "+f"(acc[mf][nf][3])
                    : "r"(a[mf][0]), "r"(a[mf][1]), "r"(a[mf][2]), "r"(a[mf][3]),
                      "r"(b[nf][0]), "r"(b[nf][1]));
            }
    }

    #pragma unroll
    for (int nf = 0; nf < 4; nf++) {
        const int col = n0 + wn + nf * 8 + tig * 2;
        const float2 bb = *(const float2*)(bias + col);
        #pragma unroll
        for (int mf = 0; mf < 2; mf++) {
            const int row = m0 + wm + mf * 16 + g;
            float2 v0 = make_float2(acc[mf][nf][0] + bb.x, acc[mf][nf][1] + bb.y);
            float2 v1 = make_float2(acc[mf][nf][2] + bb.x, acc[mf][nf][3] + bb.y);
            *(float2*)(C + (size_t)row * N + col) = v0;
            *(float2*)(C + (size_t)(row + 8) * N + col) = v1;
        }
    }
}

// W [K=256, N] fp32 row-major  ->  Wt [N, K] fp16 row-major
__global__ void pack_wt(const float* __restrict__ W, __half* __restrict__ Wt, int N) {
    __shared__ float t[32][33];
    int bx = blockIdx.x * 32;
    int by = blockIdx.y * 32;
    int x = threadIdx.x, y = threadIdx.y;
    #pragma unroll
    for (int i = 0; i < 32; i += 8)
        t[y + i][x] = W[(size_t)(by + y + i) * N + bx + x];
    __syncthreads();
    #pragma unroll
    for (int i = 0; i < 32; i += 8)
        Wt[(size_t)(bx + y + i) * GK + by + x] = __float2half_rn(t[x][y + i]);
}

// ---------------- prep: softmax + bilinear weights + clamped corner indices ----------------
__global__ void msda_prep(const float* __restrict__ qp,
                          const float* __restrict__ refpts,
                          float4* __restrict__ sw,
                          int4* __restrict__ si)
{
    int t = blockIdx.x * blockDim.x + threadIdx.x;
    if (t >= BNH) return;
    int bn = t / HNUM;

    const float* q = qp + (size_t)t * 48;

    float lg[16];
    float mx = -1e30f;
    #pragma unroll
    for (int s = 0; s < 16; s++) { lg[s] = q[s * 3 + 2]; mx = fmaxf(mx, lg[s]); }
    float sum = 0.f;
    #pragma unroll
    for (int s = 0; s < 16; s++) { lg[s] = expf(lg[s] - mx); sum += lg[s]; }
    float inv = 1.0f / sum;

    float rx = refpts[bn * 2 + 0];
    float ry = refpts[bn * 2 + 1];

    #pragma unroll
    for (int s = 0; s < 16; s++) {
        int l = s >> 2;
        int sh = c_sh[l];
        float fs = (float)sh;
        int st = c_start[l];
        float aw = lg[s] * inv;

        float px = rx + q[s * 3 + 0] / fs;
        float py = ry + q[s * 3 + 1] / fs;
        float x = px * fs - 0.5f;
        float y = py * fs - 0.5f;
        float x0f = floorf(x), y0f = floorf(y);
        int x0 = (int)x0f, y0 = (int)y0f;
        float wx = x - x0f, wy = y - y0f;

        float w00 = (1.f - wx) * (1.f - wy) * aw;
        float w10 = wx * (1.f - wy) * aw;
        float w01 = (1.f - wx) * wy * aw;
        float w11 = wx * wy * aw;

        bool vx0 = (x0 >= 0) & (x0 < sh);
        bool vx1 = (x0 + 1 >= 0) & (x0 + 1 < sh);
        bool vy0 = (y0 >= 0) & (y0 < sh);
        bool vy1 = (y0 + 1 >= 0) & (y0 + 1 < sh);

        int xc0 = min(max(x0, 0), sh - 1);
        int xc1 = min(max(x0 + 1, 0), sh - 1);
        int yc0 = min(max(y0, 0), sh - 1);
        int yc1 = min(max(y0 + 1, 0), sh - 1);

        float4 w4;
        w4.x = (vx0 & vy0) ? w00 : 0.f;
        w4.y = (vx1 & vy0) ? w10 : 0.f;
        w4.z = (vx0 & vy1) ? w01 : 0.f;
        w4.w = (vx1 & vy1) ? w11 : 0.f;

        int4 i4;
        i4.x = (st + yc0 * sh + xc0) * HIDDEN;
        i4.y = (st + yc0 * sh + xc1) * HIDDEN;
        i4.z = (st + yc1 * sh + xc0) * HIDDEN;
        i4.w = (st + yc1 * sh + xc1) * HIDDEN;

        sw[(size_t)t * 16 + s] = w4;
        si[(size_t)t * 16 + s] = i4;
    }
}

// ---------------- gather (fp16 pyramid): one warp per (b,n,h), lane = channel ----------------
__global__ __launch_bounds__(256) void msda_sample(
    const __half* __restrict__ img_p,
    const float4* __restrict__ sw,
    const int4* __restrict__ si,
    float* __restrict__ out)
{
    int w = blockIdx.x * 8 + (threadIdx.x >> 5);
    int lane = threadIdx.x & 31;

    int h = w % HNUM;
    int b = w / (NQ * HNUM);

    const __half* base = img_p + (size_t)b * ITOT * HIDDEN + h * CHD + lane;
    const float4* wp = sw + (size_t)w * 16;
    const int4*   ip = si + (size_t)w * 16;

    float acc = 0.f;
    #pragma unroll
    for (int s = 0; s < 16; s++) {
        float4 wt = __ldg(wp + s);
        int4   ix = __ldg(ip + s);
        acc += wt.x * __half2float(__ldg(base + ix.x));
        acc += wt.y * __half2float(__ldg(base + ix.y));
        acc += wt.z * __half2float(__ldg(base + ix.z));
        acc += wt.w * __half2float(__ldg(base + ix.w));
    }
    out[(size_t)w * CHD + lane] = acc;
}

// ---------------- launch ----------------
extern "C" void kernel_launch(void* const* d_in, const int* in_sizes, int n_in,
                              void* d_out, int out_size)
{
    const float* img     = (const float*)d_in[0];
    const float* queries = (const float*)d_in[2];
    const float* refpts  = (const float*)d_in[3];
    const float* W_img   = (const float*)d_in[4];
    const float* b_img   = (const float*)d_in[5];
    const float* W_q     = (const float*)d_in[6];
    const float* b_q     = (const float*)d_in[7];
    const float* W_out   = (const float*)d_in[8];
    const float* b_out   = (const float*)d_in[9];
    float* out = (float*)d_out;

    float *qp, *hidden;
    __half *img_p, *Wt1, *Wt2, *Wt3;
    float4* sw;
    int4* si;
    cudaGetSymbolAddress((void**)&img_p,  g_img_p);
    cudaGetSymbolAddress((void**)&qp,     g_qp);
    cudaGetSymbolAddress((void**)&sw,     g_sw);
    cudaGetSymbolAddress((void**)&si,     g_si);
    cudaGetSymbolAddress((void**)&hidden, g_hidden);
    cudaGetSymbolAddress((void**)&Wt1,    g_Wt1);
    cudaGetSymbolAddress((void**)&Wt2,    g_Wt2);
    cudaGetSymbolAddress((void**)&Wt3,    g_Wt3);

    // 0) pack weights
    {
        dim3 blk(32, 8);
        pack_wt<<<dim3(HIDDEN / 32, GK / 32), blk>>>(W_img, Wt1, HIDDEN);
        pack_wt<<<dim3(QPW    / 32, GK / 32), blk>>>(W_q,   Wt2, QPW);
        pack_wt<<<dim3(EMBD   / 32, GK / 32), blk>>>(W_out, Wt3, EMBD);
    }
    // 1) img projection -> fp16 img_p
    hgemm16<<<dim3(HIDDEN / 128, (BATCH * ITOT) / 128), 256>>>(img, Wt1, b_img, img_p);
    // 2) query projection (fp32 out)
    hgemm<<<dim3(QPW / 64, (BATCH * NQ) / 128), 256>>>(
        queries, Wt2, b_q, qp, BATCH * NQ, QPW);
    // 3) softmax + weights/indices precompute
    msda_prep<<<(BNH + 127) / 128, 128>>>(qp, refpts, sw, si);
    // 4) gather + attention reduce
    msda_sample<<<BNH / 8, 256>>>(img_p, sw, si, hidden);
    // 5) output projection
    hgemm<<<dim3(HIDDEN / 64, (BATCH * NQ) / 128), 256>>>(
        hidden, Wt3, b_out, out, BATCH * NQ, HIDDEN);
}

// round 7
// speedup vs baseline: 1.0084x; 1.0084x over previous
#include <cuda_runtime.h>
#include <cuda_fp16.h>
#include <cstdint>

// ---------------- problem constants (fixed by the reference) ----------------
#define EMBD   256
#define HIDDEN 256
#define HNUM   8
#define CHD    32
#define BATCH  8
#define NQ     1024
#define ITOT   21760           // 128^2 + 64^2 + 32^2 + 16^2
#define QPW    384             // H*L*P*3
#define GK     256             // K for every GEMM
#define BNH    (BATCH * NQ * HNUM)   // 65536

// ---------------- scratch (no allocations allowed) ----------------
__device__ __half  g_img_p[BATCH * ITOT * HIDDEN];   // projected pyramid, fp16 (~89 MB)
__device__ __half  g_Wt1[HIDDEN * GK];               // W_img^T [N,K] fp16
__device__ __half  g_Wt2[QPW * GK];                  // W_q^T   [N,K] fp16
__device__ __half  g_Wt3[EMBD * GK];                 // W_out^T [N,K] fp16
__device__ float   g_qp[BATCH * NQ * QPW];           // query projection
__device__ float4  g_sw[BNH * 16];                   // 4 corner weights (x attn)
__device__ int4    g_si[BNH * 16];                   // 4 corner indices (x HIDDEN)
__device__ float   g_hidden[BATCH * NQ * HIDDEN];    // sampled context

__constant__ int c_sh[4]    = {128, 64, 32, 16};
__constant__ int c_start[4] = {0, 16384, 20480, 21504};

// ---------------- helpers ----------------
__device__ __forceinline__ void cp16(uint32_t dst, const void* src) {
    asm volatile("cp.async.cg.shared.global [%0], [%1], 16;" :: "r"(dst), "l"(src));
}
__device__ __forceinline__ uint32_t smem_u32(const void* p) {
    uint32_t a;
    asm("{ .reg .u64 t; cvta.to.shared.u64 t, %1; cvt.u32.u64 %0, t; }" : "=r"(a) : "l"(p));
    return a;
}
__device__ __forceinline__ uint32_t pack_h2(float lo, float hi) {
    uint32_t r;
    asm("cvt.rn.f16x2.f32 %0, %1, %2;" : "=r"(r) : "f"(hi), "f"(lo));
    return r;
}

// ============ GEMM1: C_fp16[M,256] = A_fp32[M,256] @ Wt_fp16[256,256]^T + bias ============
// R6 structure (CTA 128x128, 8 warps 2(M)x4(N), warp tile 64x32, ldmatrix A, 3-stage),
// but MMA uses f16 ACCUMULATE (C=0 per MMA, k16 chunk) promoted into fp32 registers.
// Bet: f16-acc HMMA fallback runs 2x the f32-acc rate.

#define APITCH  24                 // halves per A/B row (16 used + 8 pad)
#define STG_H   (128 * APITCH)     // halves per stage per tile
#define NST     3
#define NKT16   (GK / 16)          // 16

__global__ __launch_bounds__(256) void hgemm16(
    const float* __restrict__ A, const __half* __restrict__ Wt,
    const float* __restrict__ bias, __half* __restrict__ C)
{
    __shared__ __half sA[NST][STG_H];   // 3 * 6 KB
    __shared__ __half sB[NST][STG_H];   // 3 * 6 KB

    const int tid = threadIdx.x;
    const int wid = tid >> 5;
    const int lane = tid & 31;
    const int g = lane >> 2;             // 0..7
    const int tig = lane & 3;            // 0..3
    const int m0 = blockIdx.y * 128;
    const int n0 = blockIdx.x * 128;
    const int wm = (wid & 1) * 64;       // warp M offset
    const int wn = (wid >> 1) * 32;      // warp N offset

    const uint32_t lds_a_off = (uint32_t)((wm + (lane & 15)) * APITCH + (lane >> 4) * 8) * 2;

    uint32_t sbA[NST], sbB[NST];
    #pragma unroll
    for (int s = 0; s < NST; s++) { sbA[s] = smem_u32(&sA[s][0]); sbB[s] = smem_u32(&sB[s][0]); }

    const int arow = tid >> 1, aseg = tid & 1;
    const float* Ab = A + (size_t)(m0 + arow) * GK + aseg * 8;
    const __half* Bb = Wt + (size_t)(n0 + arow) * GK + aseg * 8;
    const uint32_t st_off = (uint32_t)(arow * APITCH + aseg * 8) * 2;

    float4 rA[2][2];
    auto ldgA = [&](int kt, int slot) {
        const float* p = Ab + kt * 16;
        rA[slot][0] = *(const float4*)p;
        rA[slot][1] = *(const float4*)(p + 4);
    };
    auto stsA = [&](int buf, int slot) {
        uint4 v;
        v.x = pack_h2(rA[slot][0].x, rA[slot][0].y);
        v.y = pack_h2(rA[slot][0].z, rA[slot][0].w);
        v.z = pack_h2(rA[slot][1].x, rA[slot][1].y);
        v.w = pack_h2(rA[slot][1].z, rA[slot][1].w);
        *(uint4*)((char*)&sA[buf][0] + st_off) = v;
    };
    auto cpB = [&](int buf, int kt) {
        cp16(sbB[buf] + st_off, Bb + kt * 16);
    };

    float acc[4][4][4];
    #pragma unroll
    for (int i = 0; i < 4; i++)
        #pragma unroll
        for (int j = 0; j < 4; j++)
            #pragma unroll
            for (int r = 0; r < 4; r++) acc[i][j][r] = 0.f;

    // prologue
    ldgA(0, 0); ldgA(1, 1);
    cpB(0, 0);  asm volatile("cp.async.commit_group;" ::: "memory");
    cpB(1, 1);  asm volatile("cp.async.commit_group;" ::: "memory");
    stsA(0, 0); ldgA(2, 0);

    int buf = 0;
    #pragma unroll 1
    for (int kt = 0; kt < NKT16; kt++) {
        if (kt < NKT16 - 1) {
            asm volatile("cp.async.wait_group 1;" ::: "memory");
        } else {
            asm volatile("cp.async.wait_group 0;" ::: "memory");
        }
        __syncthreads();

        if (kt + 2 < NKT16) {
            int nb = buf + 2; if (nb >= NST) nb -= NST;
            cpB(nb, kt + 2);
            asm volatile("cp.async.commit_group;" ::: "memory");
        }

        // ---- fragments ----
        uint32_t a[4][4], b[4][2];
        #pragma unroll
        for (int mf = 0; mf < 4; mf++) {
            uint32_t addr = sbA[buf] + lds_a_off + (uint32_t)(mf * 16 * APITCH) * 2;
            asm volatile(
                "ldmatrix.sync.aligned.m8n8.x4.shared.b16 {%0,%1,%2,%3}, [%4];"
                : "=r"(a[mf][0]), "=r"(a[mf][1]), "=r"(a[mf][2]), "=r"(a[mf][3])
                : "r"(addr));
        }
        const __half* Bs = sB[buf];
        #pragma unroll
        for (int nf = 0; nf < 4; nf++) {
            int rb = wn + nf * 8 + g;
            b[nf][0] = *(const uint32_t*)&Bs[rb * APITCH + tig * 2];
            b[nf][1] = *(const uint32_t*)&Bs[rb * APITCH + tig * 2 + 8];
        }
        #pragma unroll
        for (int mf = 0; mf < 4; mf++)
            #pragma unroll
            for (int nf = 0; nf < 4; nf++) {
                uint32_t d0, d1;
                asm volatile(
                    "mma.sync.aligned.m16n8k16.row.col.f16.f16.f16.f16 "
                    "{%0,%1}, {%2,%3,%4,%5}, {%6,%7}, {%8,%8};"
                    : "=r"(d0), "=r"(d1)
                    : "r"(a[mf][0]), "r"(a[mf][1]), "r"(a[mf][2]), "r"(a[mf][3]),
                      "r"(b[nf][0]), "r"(b[nf][1]), "r"(0u));
                float2 f0 = __half22float2(*reinterpret_cast<__half2*>(&d0));
                float2 f1 = __half22float2(*reinterpret_cast<__half2*>(&d1));
                acc[mf][nf][0] += f0.x; acc[mf][nf][1] += f0.y;
                acc[mf][nf][2] += f1.x; acc[mf][nf][3] += f1.y;
            }

        // ---- producers for future stages ----
        if (kt + 1 < NKT16) {
            int nb = buf + 1; if (nb >= NST) nb -= NST;
            stsA(nb, (kt + 1) & 1);
        }
        if (kt + 3 < NKT16) ldgA(kt + 3, (kt + 3) & 1);

        if (++buf == NST) buf = 0;
    }

    // epilogue: bias + fp16 store
    #pragma unroll
    for (int nf = 0; nf < 4; nf++) {
        const int col = n0 + wn + nf * 8 + tig * 2;
        const float2 bb = *(const float2*)(bias + col);
        #pragma unroll
        for (int mf = 0; mf < 4; mf++) {
            const int row = m0 + wm + mf * 16 + g;
            uint32_t h0 = pack_h2(acc[mf][nf][0] + bb.x, acc[mf][nf][1] + bb.y);
            uint32_t h1 = pack_h2(acc[mf][nf][2] + bb.x, acc[mf][nf][3] + bb.y);
            *(uint32_t*)(C + (size_t)row * HIDDEN + col) = h0;
            *(uint32_t*)(C + (size_t)(row + 8) * HIDDEN + col) = h1;
        }
    }
}

// =============== fp16 mma GEMM, f32 accum (R5 kernel, GEMM2/3) ===============
#define ROWPAD  20
#define BPITCH  24
#define A_STG   (128 * ROWPAD)
#define B_STG   (64 * BPITCH)
#define NSTAGE  3
#define NKT     (GK / 16)

__global__ __launch_bounds__(256) void hgemm(
    const float* __restrict__ A, const __half* __restrict__ Wt,
    const float* __restrict__ bias, float* __restrict__ C,
    int M, int N)
{
    __shared__ float  sA[NSTAGE][A_STG];
    __shared__ __half sB[NSTAGE][B_STG];

    const int tid = threadIdx.x;
    const int wid = tid >> 5;
    const int lane = tid & 31;
    const int g = lane >> 2;
    const int tig = lane & 3;
    const int m0 = blockIdx.y * 128;
    const int n0 = blockIdx.x * 64;
    const int wm = (wid & 3) * 32;
    const int wn = (wid >> 2) * 32;

    float acc[2][4][4];
    #pragma unroll
    for (int i = 0; i < 2; i++)
        #pragma unroll
        for (int j = 0; j < 4; j++)
            #pragma unroll
            for (int r = 0; r < 4; r++) acc[i][j][r] = 0.f;

    uint32_t sbA[NSTAGE], sbB[NSTAGE];
    #pragma unroll
    for (int s = 0; s < NSTAGE; s++) {
        sbA[s] = smem_u32(&sA[s][0]);
        sbB[s] = smem_u32(&sB[s][0]);
    }

    auto load_stage = [&](int s, int kt) {
        #pragma unroll
        for (int i = 0; i < 2; i++) {
            int id = tid + i * 256;
            int row = id >> 2, c = id & 3;
            cp16(sbA[s] + (uint32_t)(row * ROWPAD + c * 4) * 4,
                 A + (size_t)(m0 + row) * GK + kt * 16 + c * 4);
        }
        if (tid < 128) {
            int row = tid >> 1, c = tid & 1;
            cp16(sbB[s] + (uint32_t)(row * BPITCH + c * 8) * 2,
                 Wt + (size_t)(n0 + row) * GK + kt * 16 + c * 8);
        }
    };

    load_stage(0, 0);
    asm volatile("cp.async.commit_group;" ::: "memory");
    load_stage(1, 1);
    asm volatile("cp.async.commit_group;" ::: "memory");

    #pragma unroll 1
    for (int kt = 0; kt < NKT; kt++) {
        if (kt < NKT - 1) {
            asm volatile("cp.async.wait_group 1;" ::: "memory");
        } else {
            asm volatile("cp.async.wait_group 0;" ::: "memory");
        }
        __syncthreads();

        if (kt + 2 < NKT) {
            load_stage((kt + 2) % NSTAGE, kt + 2);
            asm volatile("cp.async.commit_group;" ::: "memory");
        }

        const float*  As = sA[kt % NSTAGE];
        const __half* Bs = sB[kt % NSTAGE];

        uint32_t a[2][4], b[4][2];
        #pragma unroll
        for (int mf = 0; mf < 2; mf++) {
            int r = wm + mf * 16 + g;
            a[mf][0] = pack_h2(As[r * ROWPAD + tig * 2], As[r * ROWPAD + tig * 2 + 1]);
            a[mf][1] = pack_h2(As[(r + 8) * ROWPAD + tig * 2], As[(r + 8) * ROWPAD + tig * 2 + 1]);
            a[mf][2] = pack_h2(As[r * ROWPAD + tig * 2 + 8], As[r * ROWPAD + tig * 2 + 9]);
            a[mf][3] = pack_h2(As[(r + 8) * ROWPAD + tig * 2 + 8], As[(r + 8) * ROWPAD + tig * 2 + 9]);
        }
        #pragma unroll
        for (int nf = 0; nf < 4; nf++) {
            int rb = wn + nf * 8 + g;
            b[nf][0] = *(const uint32_t*)&Bs[rb * BPITCH + tig * 2];
            b[nf][1] = *(const uint32_t*)&Bs[rb * BPITCH + tig * 2 + 8];
        }
        #pragma unroll
        for (int mf = 0; mf < 2; mf++)
            #pragma unroll
            for (int nf = 0; nf < 4; nf++) {
                asm volatile(
                    "mma.sync.aligned.m16n8k16.row.col.f32.f16.f16.f32 "
                    "{%0,%1,%2,%3}, {%4,%5,%6,%7}, {%8,%9}, {%0,%1,%2,%3};"
                    : "+f"(acc[mf][nf][0]), "+f"(acc[mf][nf][1]),
                      "+f"(acc[mf][nf][2]), "+f"(acc[mf][nf][3])
                    : "r"(a[mf][0]), "r"(a[mf][1]), "r"(a[mf][2]), "r"(a[mf][3]),
                      "r"(b[nf][0]), "r"(b[nf][1]));
            }
    }

    #pragma unroll
    for (int nf = 0; nf < 4; nf++) {
        const int col = n0 + wn + nf * 8 + tig * 2;
        const float2 bb = *(const float2*)(bias + col);
        #pragma unroll
        for (int mf = 0; mf < 2; mf++) {
            const int row = m0 + wm + mf * 16 + g;
            float2 v0 = make_float2(acc[mf][nf][0] + bb.x, acc[mf][nf][1] + bb.y);
            float2 v1 = make_float2(acc[mf][nf][2] + bb.x, acc[mf][nf][3] + bb.y);
            *(float2*)(C + (size_t)row * N + col) = v0;
            *(float2*)(C + (size_t)(row + 8) * N + col) = v1;
        }
    }
}

// W [K=256, N] fp32 row-major  ->  Wt [N, K] fp16 row-major
__global__ void pack_wt(const float* __restrict__ W, __half* __restrict__ Wt, int N) {
    __shared__ float t[32][33];
    int bx = blockIdx.x * 32;
    int by = blockIdx.y * 32;
    int x = threadIdx.x, y = threadIdx.y;
    #pragma unroll
    for (int i = 0; i < 32; i += 8)
        t[y + i][x] = W[(size_t)(by + y + i) * N + bx + x];
    __syncthreads();
    #pragma unroll
    for (int i = 0; i < 32; i += 8)
        Wt[(size_t)(bx + y + i) * GK + by + x] = __float2half_rn(t[x][y + i]);
}

// ---------------- prep: softmax + bilinear weights + clamped corner indices ----------------
__global__ void msda_prep(const float* __restrict__ qp,
                          const float* __restrict__ refpts,
                          float4* __restrict__ sw,
                          int4* __restrict__ si)
{
    int t = blockIdx.x * blockDim.x + threadIdx.x;
    if (t >= BNH) return;
    int bn = t / HNUM;

    const float* q = qp + (size_t)t * 48;

    float lg[16];
    float mx = -1e30f;
    #pragma unroll
    for (int s = 0; s < 16; s++) { lg[s] = q[s * 3 + 2]; mx = fmaxf(mx, lg[s]); }
    float sum = 0.f;
    #pragma unroll
    for (int s = 0; s < 16; s++) { lg[s] = expf(lg[s] - mx); sum += lg[s]; }
    float inv = 1.0f / sum;

    float rx = refpts[bn * 2 + 0];
    float ry = refpts[bn * 2 + 1];

    #pragma unroll
    for (int s = 0; s < 16; s++) {
        int l = s >> 2;
        int sh = c_sh[l];
        float fs = (float)sh;
        int st = c_start[l];
        float aw = lg[s] * inv;

        float px = rx + q[s * 3 + 0] / fs;
        float py = ry + q[s * 3 + 1] / fs;
        float x = px * fs - 0.5f;
        float y = py * fs - 0.5f;
        float x0f = floorf(x), y0f = floorf(y);
        int x0 = (int)x0f, y0 = (int)y0f;
        float wx = x - x0f, wy = y - y0f;

        float w00 = (1.f - wx) * (1.f - wy) * aw;
        float w10 = wx * (1.f - wy) * aw;
        float w01 = (1.f - wx) * wy * aw;
        float w11 = wx * wy * aw;

        bool vx0 = (x0 >= 0) & (x0 < sh);
        bool vx1 = (x0 + 1 >= 0) & (x0 + 1 < sh);
        bool vy0 = (y0 >= 0) & (y0 < sh);
        bool vy1 = (y0 + 1 >= 0) & (y0 + 1 < sh);

        int xc0 = min(max(x0, 0), sh - 1);
        int xc1 = min(max(x0 + 1, 0), sh - 1);
        int yc0 = min(max(y0, 0), sh - 1);
        int yc1 = min(max(y0 + 1, 0), sh - 1);

        float4 w4;
        w4.x = (vx0 & vy0) ? w00 : 0.f;
        w4.y = (vx1 & vy0) ? w10 : 0.f;
        w4.z = (vx0 & vy1) ? w01 : 0.f;
        w4.w = (vx1 & vy1) ? w11 : 0.f;

        int4 i4;
        i4.x = (st + yc0 * sh + xc0) * HIDDEN;
        i4.y = (st + yc0 * sh + xc1) * HIDDEN;
        i4.z = (st + yc1 * sh + xc0) * HIDDEN;
        i4.w = (st + yc1 * sh + xc1) * HIDDEN;

        sw[(size_t)t * 16 + s] = w4;
        si[(size_t)t * 16 + s] = i4;
    }
}

// ---------------- gather: one warp covers TWO heads (half2 channels) ----------------
// lane 0-15 -> head pair member 0, lane 16-31 -> member 1; each lane = 2 channels.
__global__ __launch_bounds__(256) void msda_sample2(
    const __half* __restrict__ img_p,
    const float4* __restrict__ sw,
    const int4* __restrict__ si,
    float* __restrict__ out)
{
    int w2 = blockIdx.x * 8 + (threadIdx.x >> 5);   // head-pair id, [0, BNH/2)
    int lane = threadIdx.x & 31;
    int hp = lane >> 4;                              // 0 or 1
    int ch2 = lane & 15;                             // half2 channel index

    int t = w2 * 2 + hp;                             // (b*NQ+n)*HNUM + h
    int h = t & (HNUM - 1);
    int b = t / (NQ * HNUM);

    const __half* base = img_p + (size_t)b * ITOT * HIDDEN + h * CHD + ch2 * 2;
    const float4* wp = sw + (size_t)t * 16;
    const int4*   ip = si + (size_t)t * 16;

    float2 acc = make_float2(0.f, 0.f);
    #pragma unroll
    for (int s = 0; s < 16; s++) {
        float4 wt = __ldg(wp + s);
        int4   ix = __ldg(ip + s);
        float2 v0 = __half22float2(*(const __half2*)(base + ix.x));
        float2 v1 = __half22float2(*(const __half2*)(base + ix.y));
        float2 v2 = __half22float2(*(const __half2*)(base + ix.z));
        float2 v3 = __half22float2(*(const __half2*)(base + ix.w));
        acc.x += wt.x * v0.x + wt.y * v1.x + wt.z * v2.x + wt.w * v3.x;
        acc.y += wt.x * v0.y + wt.y * v1.y + wt.z * v2.y + wt.w * v3.y;
    }
    *(float2*)(out + (size_t)t * CHD + ch2 * 2) = acc;
}

// ---------------- launch ----------------
extern "C" void kernel_launch(void* const* d_in, const int* in_sizes, int n_in,
                              void* d_out, int out_size)
{
    const float* img     = (const float*)d_in[0];
    const float* queries = (const float*)d_in[2];
    const float* refpts  = (const float*)d_in[3];
    const float* W_img   = (const float*)d_in[4];
    const float* b_img   = (const float*)d_in[5];
    const float* W_q     = (const float*)d_in[6];
    const float* b_q     = (const float*)d_in[7];
    const float* W_out   = (const float*)d_in[8];
    const float* b_out   = (const float*)d_in[9];
    float* out = (float*)d_out;

    float *qp, *hidden;
    __half *img_p, *Wt1, *Wt2, *Wt3;
    float4* sw;
    int4* si;
    cudaGetSymbolAddress((void**)&img_p,  g_img_p);
    cudaGetSymbolAddress((void**)&qp,     g_qp);
    cudaGetSymbolAddress((void**)&sw,     g_sw);
    cudaGetSymbolAddress((void**)&si,     g_si);
    cudaGetSymbolAddress((void**)&hidden, g_hidden);
    cudaGetSymbolAddress((void**)&Wt1,    g_Wt1);
    cudaGetSymbolAddress((void**)&Wt2,    g_Wt2);
    cudaGetSymbolAddress((void**)&Wt3,    g_Wt3);

    // 0) pack weights
    {
        dim3 blk(32, 8);
        pack_wt<<<dim3(HIDDEN / 32, GK / 32), blk>>>(W_img, Wt1, HIDDEN);
        pack_wt<<<dim3(QPW    / 32, GK / 32), blk>>>(W_q,   Wt2, QPW);
        pack_wt<<<dim3(EMBD   / 32, GK / 32), blk>>>(W_out, Wt3, EMBD);
    }
    // 1) img projection -> fp16 img_p  (f16-acc MMA, chunked fp32 promotion)
    hgemm16<<<dim3(HIDDEN / 128, (BATCH * ITOT) / 128), 256>>>(img, Wt1, b_img, img_p);
    // 2) query projection (fp32 out)
    hgemm<<<dim3(QPW / 64, (BATCH * NQ) / 128), 256>>>(
        queries, Wt2, b_q, qp, BATCH * NQ, QPW);
    // 3) softmax + weights/indices precompute
    msda_prep<<<(BNH + 127) / 128, 128>>>(qp, refpts, sw, si);
    // 4) gather + attention reduce (2 heads per warp)
    msda_sample2<<<(BNH / 2) / 8, 256>>>(img_p, sw, si, hidden);
    // 5) output projection
    hgemm<<<dim3(HIDDEN / 64, (BATCH * NQ) / 128), 256>>>(
        hidden, Wt3, b_out, out, BATCH * NQ, HIDDEN);
}